// round 3
// baseline (speedup 1.0000x reference)
#include <cuda_runtime.h>
#include <math.h>

#define S_LEN 1024
#define B_SZ  128
#define D_IN  64
#define H_SZ  512
#define NCTA  128

typedef unsigned long long ull;

// ------------------------- device scratch (allocation-free rule) -------------
__device__ float g_xT[S_LEN * D_IN * B_SZ];                 // [S][D][B]   32 MB
__device__ float g_h1[(size_t)S_LEN * H_SZ * B_SZ];         // [S][H][B]  256 MB
__device__ float g_h2[(size_t)S_LEN * H_SZ * B_SZ];         // [S][H][B]  256 MB
__device__ float g_hbuf[2][H_SZ * B_SZ];                    // double-buffered h
__device__ float g_e[B_SZ * S_LEN];                         // energies [B][S]
__device__ float g_att[B_SZ * S_LEN];                       // entmax weights
__device__ float g_pc[64 * 128 * 128];                      // partial contexts
__device__ float g_ctx[H_SZ * B_SZ];                        // context [H][B]
__device__ unsigned g_bar_count;
__device__ unsigned g_bar_gen;

// ------------------------- f32x2 helpers -------------------------------------
__device__ __forceinline__ ull dup2(float v) {
    ull r; asm("mov.b64 %0, {%1, %1};" : "=l"(r) : "f"(v)); return r;
}
__device__ __forceinline__ ull pk2(float lo, float hi) {
    ull r; asm("mov.b64 %0, {%1, %2};" : "=l"(r) : "f"(lo), "f"(hi)); return r;
}
__device__ __forceinline__ void unpk(ull v, float& lo, float& hi) {
    asm("mov.b64 {%0, %1}, %2;" : "=f"(lo), "=f"(hi) : "l"(v));
}
__device__ __forceinline__ ull fma2(ull a, ull b, ull c) {
    ull d; asm("fma.rn.f32x2 %0, %1, %2, %3;" : "=l"(d) : "l"(a), "l"(b), "l"(c));
    return d;
}
__device__ __forceinline__ float sigf(float v) { return 1.0f / (1.0f + expf(-v)); }

// ------------------------- grid barrier (all-atomic, generation based) -------
// Requires all NCTA CTAs co-resident: 128 CTAs <= 148 SMs, 1 wave guaranteed.
__device__ __forceinline__ unsigned gen_read() {
    unsigned v;
    asm volatile("ld.acquire.gpu.u32 %0, [%1];" : "=r"(v) : "l"(&g_bar_gen) : "memory");
    return v;
}
__device__ __forceinline__ void grid_barrier() {
    __syncthreads();
    if (threadIdx.x == 0) {
        unsigned target = gen_read() + 1u;          // read BEFORE arriving
        __threadfence();
        unsigned old = atomicAdd(&g_bar_count, 1u);
        if (old == NCTA - 1u) {
            atomicExch(&g_bar_count, 0u);
            __threadfence();
            atomicExch(&g_bar_gen, target);         // publish release
        } else {
            while ((int)(gen_read() - target) < 0) { __nanosleep(40); }
        }
        __threadfence();
    }
    __syncthreads();
}

// ------------------------- transpose x[B][S][D] -> xT[S][D][B] ---------------
__global__ void transpose_kernel(const float* __restrict__ x) {
    int idx = blockIdx.x * 256 + threadIdx.x;
    if (idx < S_LEN * D_IN * B_SZ) {
        int b = idx & (B_SZ - 1);
        int sd = idx >> 7;
        int d = sd & (D_IN - 1);
        int s = sd >> 6;
        g_xT[idx] = x[((size_t)b * S_LEN + s) * D_IN + d];
    }
}

// ------------------------- persistent LSTM layer -----------------------------
// CTA = 8 h-columns x 64 batches -> 32 gate rows. Weights in SMEM for all steps.
// Thread: 1 h-column (j = tid>>4), 4 batches (b0 = bbase + (tid&15)*4).
template <int KIN>
__global__ __launch_bounds__(128, 1) void lstm_kernel(
    const float* __restrict__ W_ih, const float* __restrict__ W_hh,
    const float* __restrict__ b_ih, const float* __restrict__ b_hh)
{
    constexpr int K = KIN + H_SZ;
    extern __shared__ float wsm[];          // [32][K]
    __shared__ float bsm[32];

    const float* inSeq = (KIN == D_IN) ? g_xT : g_h1;
    float* outSeq      = (KIN == D_IN) ? g_h1 : g_h2;

    const int tid = threadIdx.x;
    const int cid = blockIdx.x;
    const int hg = cid >> 1;                // 0..63
    const int bg = cid & 1;                 // 0..1
    const int hi0 = hg * 8;
    const int bbase = bg * 64;

    // load this CTA's 32 gate-row weights: row (t*8+j) -> global gate row t*512+hi0+j
    for (int idx = tid; idx < 32 * K; idx += 128) {
        int row = idx / K;
        int k = idx - row * K;
        int t = row >> 3, j = row & 7;
        int r = t * H_SZ + hi0 + j;
        wsm[idx] = (k < KIN) ? W_ih[(size_t)r * KIN + k]
                             : W_hh[(size_t)r * H_SZ + (k - KIN)];
    }
    if (tid < 32) {
        int t = tid >> 3, j = tid & 7;
        int r = t * H_SZ + hi0 + j;
        bsm[tid] = b_ih[r] + b_hh[r];
    }

    const int j  = tid >> 4;                     // 0..7
    const int b0 = bbase + (tid & 15) * 4;       // 4 batches
    const int hi = hi0 + j;

    // zero initial hidden state (our slice), then global barrier
    *(float4*)&g_hbuf[0][hi * B_SZ + b0] = make_float4(0.f, 0.f, 0.f, 0.f);
    __syncthreads();
    grid_barrier();

    float c[4] = {0.f, 0.f, 0.f, 0.f};
    const float* wrow = wsm + (size_t)j * K;     // t' stride = 8*K

    for (int st = 0; st < S_LEN; ++st) {
        const float* inA = inSeq + (size_t)st * KIN * B_SZ + b0;
        const float* inB = g_hbuf[st & 1] + b0;
        float* hOut = g_hbuf[(st + 1) & 1];

        ull a01[4], a23[4];
#pragma unroll
        for (int q = 0; q < 4; ++q) { a01[q] = dup2(bsm[q * 8 + j]); a23[q] = a01[q]; }

#pragma unroll 4
        for (int k = 0; k < KIN; ++k) {
            float4 v = *(const float4*)(inA + (size_t)k * B_SZ);
            ull v01 = pk2(v.x, v.y), v23 = pk2(v.z, v.w);
#pragma unroll
            for (int q = 0; q < 4; ++q) {
                ull w = dup2(wrow[q * 8 * K + k]);
                a01[q] = fma2(w, v01, a01[q]);
                a23[q] = fma2(w, v23, a23[q]);
            }
        }
#pragma unroll 4
        for (int k = 0; k < H_SZ; ++k) {
            float4 v = *(const float4*)(inB + (size_t)k * B_SZ);
            ull v01 = pk2(v.x, v.y), v23 = pk2(v.z, v.w);
#pragma unroll
            for (int q = 0; q < 4; ++q) {
                ull w = dup2(wrow[q * 8 * K + KIN + k]);
                a01[q] = fma2(w, v01, a01[q]);
                a23[q] = fma2(w, v23, a23[q]);
            }
        }

        float g[4][4];
#pragma unroll
        for (int q = 0; q < 4; ++q) {
            unpk(a01[q], g[q][0], g[q][1]);
            unpk(a23[q], g[q][2], g[q][3]);
        }
        float hv[4];
#pragma unroll
        for (int b = 0; b < 4; ++b) {
            float cn = sigf(g[1][b]) * c[b] + sigf(g[0][b]) * tanhf(g[2][b]);
            hv[b] = sigf(g[3][b]) * tanhf(cn);
            c[b] = cn;
        }
        float4 h4 = make_float4(hv[0], hv[1], hv[2], hv[3]);
        *(float4*)&hOut[hi * B_SZ + b0] = h4;
        *(float4*)&outSeq[(size_t)st * H_SZ * B_SZ + (size_t)hi * B_SZ + b0] = h4;

        grid_barrier();
    }
}

// ------------------------- attention energies --------------------------------
// Per-CTA (one s): T = tanh(W_a @ h2[s] + b_a) [512g x 128b], e[b] = v . T[:,b] + b_v
__global__ __launch_bounds__(256) void energy_kernel(
    const float* __restrict__ Wa, const float* __restrict__ ba,
    const float* __restrict__ va, const float* __restrict__ bv)
{
    const int s = blockIdx.x;
    const int tid = threadIdx.x;
    const int tx = tid & 15, ty = tid >> 4;
    __shared__ float sWa[32][132];
    __shared__ float sIn[32][132];
    __shared__ float red[16][128];
    const float* h2s = g_h2 + (size_t)s * H_SZ * B_SZ;

    float epart[8];
#pragma unroll
    for (int q = 0; q < 8; ++q) epart[q] = 0.f;

    for (int gc = 0; gc < 4; ++gc) {
        const int g0 = gc * 128;
        float acc[8][8];
#pragma unroll
        for (int i = 0; i < 8; ++i)
#pragma unroll
            for (int q = 0; q < 8; ++q) acc[i][q] = 0.f;

        for (int kt = 0; kt < 16; ++kt) {
            const int k0 = kt * 32;
            __syncthreads();
            for (int idx = tid; idx < 4096; idx += 256) {
                int gg = idx >> 5, kk = idx & 31;
                sWa[kk][gg] = Wa[(size_t)(g0 + gg) * H_SZ + k0 + kk];
            }
            for (int idx = tid; idx < 4096; idx += 256) {
                int kk = idx >> 7, bb = idx & 127;
                sIn[kk][bb] = h2s[(size_t)(k0 + kk) * B_SZ + bb];
            }
            __syncthreads();
#pragma unroll 4
            for (int k = 0; k < 32; ++k) {
                float4 w0 = *(float4*)&sWa[k][tx * 8];
                float4 w1 = *(float4*)&sWa[k][tx * 8 + 4];
                float4 i0 = *(float4*)&sIn[k][ty * 8];
                float4 i1 = *(float4*)&sIn[k][ty * 8 + 4];
                float wv[8] = {w0.x, w0.y, w0.z, w0.w, w1.x, w1.y, w1.z, w1.w};
                float iv[8] = {i0.x, i0.y, i0.z, i0.w, i1.x, i1.y, i1.z, i1.w};
#pragma unroll
                for (int i = 0; i < 8; ++i)
#pragma unroll
                    for (int q = 0; q < 8; ++q) acc[i][q] += wv[i] * iv[q];
            }
        }
        // epilogue: tanh, scale by v, reduce over this chunk's g
#pragma unroll
        for (int i = 0; i < 8; ++i) {
            int gidx = g0 + tx * 8 + i;
            float gv = va[gidx], bav = ba[gidx];
#pragma unroll
            for (int q = 0; q < 8; ++q) epart[q] += gv * tanhf(acc[i][q] + bav);
        }
    }
    __syncthreads();
#pragma unroll
    for (int q = 0; q < 8; ++q) red[tx][ty * 8 + q] = epart[q];
    __syncthreads();
    if (tid < 128) {
        float e = bv[0];
#pragma unroll
        for (int t = 0; t < 16; ++t) e += red[t][tid];
        g_e[(size_t)tid * S_LEN + s] = e;
    }
}

// ------------------------- entmax15 (faithful to reference) ------------------
__global__ __launch_bounds__(512) void entmax_kernel(float* __restrict__ dout)
{
    const int b = blockIdx.x;
    const int tid = threadIdx.x;
    __shared__ float xs[1024], xo[1024], sa[1024], sb[1024];
    __shared__ float rf[512];
    __shared__ int ri[512];
    const float* row = g_e + (size_t)b * S_LEN;

    xo[tid] = row[tid];
    xo[tid + 512] = row[tid + 512];
    __syncthreads();
    rf[tid] = fmaxf(xo[tid], xo[tid + 512]);
    __syncthreads();
    for (int off = 256; off > 0; off >>= 1) {
        if (tid < off) rf[tid] = fmaxf(rf[tid], rf[tid + off]);
        __syncthreads();
    }
    float mx = rf[0];
    __syncthreads();
    xo[tid] -= mx; xo[tid + 512] -= mx;
    xs[tid] = xo[tid]; xs[tid + 512] = xo[tid + 512];
    __syncthreads();

    // bitonic sort descending
    for (int k = 2; k <= 1024; k <<= 1) {
        for (int jj = k >> 1; jj > 0; jj >>= 1) {
            for (int i = tid; i < 1024; i += 512) {
                int ixj = i ^ jj;
                if (ixj > i) {
                    bool up = ((i & k) == 0);       // descending blocks
                    float a = xs[i], c2 = xs[ixj];
                    bool sw = up ? (a < c2) : (a > c2);
                    if (sw) { xs[i] = c2; xs[ixj] = a; }
                }
            }
            __syncthreads();
        }
    }

    // inclusive scan (Hillis-Steele, ping-pong)
    sa[tid] = xs[tid]; sa[tid + 512] = xs[tid + 512];
    __syncthreads();
    float* pa = sa; float* pb = sb;
    for (int off = 1; off < 1024; off <<= 1) {
        for (int i = tid; i < 1024; i += 512)
            pb[i] = pa[i] + ((i >= off) ? pa[i - off] : 0.f);
        __syncthreads();
        float* t = pa; pa = pb; pb = t;
    }

    // support count
    int cnt = 0;
    for (int i = tid; i < 1024; i += 512) {
        float sup = (float)(i + 1) * xs[i] - pa[i] + 0.5f;
        if (sup > 0.f) cnt++;
    }
    ri[tid] = cnt;
    __syncthreads();
    for (int off = 256; off > 0; off >>= 1) {
        if (tid < off) ri[tid] += ri[tid + off];
        __syncthreads();
    }
    int ssize = ri[0];
    if (ssize < 1) ssize = 1;
    if (ssize > 1023) ssize = 1023;
    // tau = support_thresh[ssize]  (reference indexes at position `ssize`)
    float tau = ((float)(ssize + 1) * xs[ssize] - pa[ssize] + 0.5f) / (float)(ssize + 1);

    float d0 = xo[tid] - tau;
    float d1 = xo[tid + 512] - tau;
    float y0 = d0 > 0.f ? sqrtf(d0) : 0.f;
    float y1 = d1 > 0.f ? sqrtf(d1) : 0.f;
    __syncthreads();
    rf[tid] = y0 + y1;
    __syncthreads();
    for (int off = 256; off > 0; off >>= 1) {
        if (tid < off) rf[tid] += rf[tid + off];
        __syncthreads();
    }
    float inv = 1.f / rf[0];
    float w0 = y0 * inv, w1 = y1 * inv;
    g_att[(size_t)b * S_LEN + tid] = w0;
    g_att[(size_t)b * S_LEN + tid + 512] = w1;
    dout[128 + (size_t)b * S_LEN + tid] = w0;
    dout[128 + (size_t)b * S_LEN + tid + 512] = w1;
}

// ------------------------- context stage 1: partial sums over s-chunks -------
__global__ __launch_bounds__(256) void ctx1_kernel()
{
    __shared__ float sAtt[64 * 128];
    const int bid = blockIdx.x;          // 64 CTAs = 16 s-chunks x 4 h-quarters
    const int ch = bid >> 2, hq = bid & 3;
    const int s0 = ch * 64, h0 = hq * 128;
    const int tid = threadIdx.x;

    for (int idx = tid; idx < 64 * 128; idx += 256) {
        int sl = idx >> 7, bb = idx & 127;
        sAtt[idx] = g_att[(size_t)bb * S_LEN + s0 + sl];
    }
    __syncthreads();

    float racc[64];
#pragma unroll
    for (int u = 0; u < 64; ++u) racc[u] = 0.f;

    const int bcol = tid & 127;
    for (int sl = 0; sl < 64; ++sl) {
        const float* src = g_h2 + ((size_t)(s0 + sl) * H_SZ + h0) * B_SZ;
        float av = sAtt[sl * 128 + bcol];
#pragma unroll 8
        for (int u = 0; u < 64; ++u)
            racc[u] += av * __ldg(src + tid + u * 256);
    }
#pragma unroll
    for (int u = 0; u < 64; ++u)
        g_pc[(size_t)bid * 16384 + tid + u * 256] = racc[u];
}

// ------------------------- context stage 2 + FC ------------------------------
__global__ void ctx2_kernel()
{
    int e = blockIdx.x * 256 + threadIdx.x;
    if (e < H_SZ * B_SZ) {
        int h = e >> 7, bb = e & 127;
        int hq = h >> 7, hl = h & 127;
        float s = 0.f;
#pragma unroll
        for (int ch = 0; ch < 16; ++ch)
            s += g_pc[((size_t)(ch * 4 + hq) * 16384) + hl * 128 + bb];
        g_ctx[e] = s;
    }
}

__global__ void fc_kernel(const float* __restrict__ fcW,
                          const float* __restrict__ fcb,
                          float* __restrict__ out)
{
    int b = threadIdx.x;   // 128 threads
    float a = fcb[0];
    for (int h = 0; h < H_SZ; ++h) a += fcW[h] * g_ctx[h * B_SZ + b];
    out[b] = a;
}

// ------------------------- launch --------------------------------------------
extern "C" void kernel_launch(void* const* d_in, const int* in_sizes, int n_in,
                              void* d_out, int out_size)
{
    (void)in_sizes; (void)n_in; (void)out_size;
    const float* x     = (const float*)d_in[0];
    const float* W_ih0 = (const float*)d_in[1];
    const float* W_hh0 = (const float*)d_in[2];
    const float* b_ih0 = (const float*)d_in[3];
    const float* b_hh0 = (const float*)d_in[4];
    const float* W_ih1 = (const float*)d_in[5];
    const float* W_hh1 = (const float*)d_in[6];
    const float* b_ih1 = (const float*)d_in[7];
    const float* b_hh1 = (const float*)d_in[8];
    const float* W_a   = (const float*)d_in[9];
    const float* b_a   = (const float*)d_in[10];
    const float* v_a   = (const float*)d_in[11];
    const float* b_v   = (const float*)d_in[12];
    const float* fc_W  = (const float*)d_in[13];
    const float* fc_b  = (const float*)d_in[14];
    float* out = (float*)d_out;

    const int smem0 = 32 * (D_IN + H_SZ) * 4;   //  73,728 B
    const int smem1 = 32 * (H_SZ + H_SZ) * 4;   // 131,072 B
    cudaFuncSetAttribute(lstm_kernel<D_IN>, cudaFuncAttributeMaxDynamicSharedMemorySize, smem0);
    cudaFuncSetAttribute(lstm_kernel<H_SZ>, cudaFuncAttributeMaxDynamicSharedMemorySize, smem1);

    transpose_kernel<<<(S_LEN * D_IN * B_SZ + 255) / 256, 256>>>(x);
    lstm_kernel<D_IN><<<NCTA, 128, smem0>>>(W_ih0, W_hh0, b_ih0, b_hh0);
    lstm_kernel<H_SZ><<<NCTA, 128, smem1>>>(W_ih1, W_hh1, b_ih1, b_hh1);
    energy_kernel<<<S_LEN, 256>>>(W_a, b_a, v_a, b_v);
    entmax_kernel<<<B_SZ, 512>>>(out);
    ctx1_kernel<<<64, 256>>>();
    ctx2_kernel<<<(H_SZ * B_SZ + 255) / 256, 256>>>();
    fc_kernel<<<1, 128>>>(fc_W, fc_b, out);
}

// round 5
// speedup vs baseline: 3.3437x; 3.3437x over previous
#include <cuda_runtime.h>
#include <math.h>

#define S_LEN 1024
#define B_SZ  128
#define D_IN  64
#define H_SZ  512
#define NCTA  128
#define CHUNK 64

typedef unsigned long long ull;

// ------------------------- device scratch (allocation-free rule) -------------
__device__ float g_xT[S_LEN * D_IN * B_SZ];                 // [S][D][B]   32 MB
__device__ float g_h1[(size_t)S_LEN * H_SZ * B_SZ];         // [S][H][B]  256 MB
__device__ float g_h2[(size_t)S_LEN * H_SZ * B_SZ];         // [S][H][B]  256 MB
__device__ float g_hbuf[2][H_SZ * B_SZ];                    // double-buffered h
__device__ float g_e[B_SZ * S_LEN];                         // energies [B][S]
__device__ float g_att[B_SZ * S_LEN];                       // entmax weights
__device__ float g_pc[64 * 128 * 128];                      // partial contexts
__device__ float g_ctx[H_SZ * B_SZ];                        // context [H][B]
__device__ unsigned g_bar_count;
__device__ unsigned g_bar_gen;

// ------------------------- f32x2 helpers -------------------------------------
__device__ __forceinline__ ull dup2(float v) {
    ull r; asm("mov.b64 %0, {%1, %1};" : "=l"(r) : "f"(v)); return r;
}
__device__ __forceinline__ ull pk2(float lo, float hi) {
    ull r; asm("mov.b64 %0, {%1, %2};" : "=l"(r) : "f"(lo), "f"(hi)); return r;
}
__device__ __forceinline__ void unpk(ull v, float& lo, float& hi) {
    asm("mov.b64 {%0, %1}, %2;" : "=f"(lo), "=f"(hi) : "l"(v));
}
__device__ __forceinline__ ull fma2(ull a, ull b, ull c) {
    ull d; asm("fma.rn.f32x2 %0, %1, %2, %3;" : "=l"(d) : "l"(a), "l"(b), "l"(c));
    return d;
}
__device__ __forceinline__ float sigf(float v) { return 1.0f / (1.0f + expf(-v)); }

// ------------------------- cp.async helpers ----------------------------------
__device__ __forceinline__ void cpa16(float* smem_dst, const float* gmem_src) {
    unsigned s = (unsigned)__cvta_generic_to_shared(smem_dst);
    asm volatile("cp.async.cg.shared.global [%0], [%1], 16;" :: "r"(s), "l"(gmem_src));
}
#define CP_COMMIT() asm volatile("cp.async.commit_group;" ::: "memory")
#define CP_WAIT1()  asm volatile("cp.async.wait_group 1;" ::: "memory")
#define CP_WAIT0()  asm volatile("cp.async.wait_group 0;" ::: "memory")

// ------------------------- grid barrier (all-atomic, generation based) -------
__device__ __forceinline__ unsigned gen_read() {
    unsigned v;
    asm volatile("ld.acquire.gpu.u32 %0, [%1];" : "=r"(v) : "l"(&g_bar_gen) : "memory");
    return v;
}
__device__ __forceinline__ void grid_barrier() {
    __syncthreads();
    if (threadIdx.x == 0) {
        unsigned target = gen_read() + 1u;          // read BEFORE arriving
        __threadfence();
        unsigned old = atomicAdd(&g_bar_count, 1u);
        if (old == NCTA - 1u) {
            atomicExch(&g_bar_count, 0u);
            __threadfence();
            atomicExch(&g_bar_gen, target);         // publish release
        } else {
            while ((int)(gen_read() - target) < 0) { __nanosleep(32); }
        }
        __threadfence();
    }
    __syncthreads();
}

// ------------------------- transpose x[B][S][D] -> xT[S][D][B] ---------------
__global__ void transpose_kernel(const float* __restrict__ x) {
    int idx = blockIdx.x * 256 + threadIdx.x;
    if (idx < S_LEN * D_IN * B_SZ) {
        int b = idx & (B_SZ - 1);
        int sd = idx >> 7;
        int d = sd & (D_IN - 1);
        int s = sd >> 6;
        g_xT[idx] = x[((size_t)b * S_LEN + s) * D_IN + d];
    }
}

// ------------------------- persistent LSTM layer -----------------------------
// CTA = 8 h-columns x 64 batches -> 32 gate rows. Weights in SMEM (gate-
// interleaved) for all steps; input vector streamed via cp.async double buffer.
// 256 threads: j = tid>>5 (h-col 0..7), lane = tid&31, 2 batches per thread.
template <int KIN>
__global__ __launch_bounds__(256, 1) void lstm_kernel(
    const float* __restrict__ W_ih, const float* __restrict__ W_hh,
    const float* __restrict__ b_ih, const float* __restrict__ b_hh)
{
    constexpr int K = KIN + H_SZ;
    constexpr int NCH = K / CHUNK;
    extern __shared__ float wsm[];                 // [8 j][K][4 t] gate-interleaved
    float* vbuf = wsm + 32 * K;                    // 2 x [CHUNK][64]
    __shared__ float bsm[32];                      // [j][t]

    const float* inSeq = (KIN == D_IN) ? g_xT : g_h1;
    float* outSeq      = (KIN == D_IN) ? g_h1 : g_h2;

    const int tid = threadIdx.x;
    const int cid = blockIdx.x;
    const int hg = cid >> 1;
    const int bg = cid & 1;
    const int hi0 = hg * 8;
    const int bbase = bg * 64;

    // weights: gate row r = t*H + hi0 + j, element k  ->  wsm[(j*K + k)*4 + t]
    for (int idx = tid; idx < 32 * K; idx += 256) {
        int row = idx / K;              // row = t*8 + j
        int k = idx - row * K;
        int t = row >> 3, j = row & 7;
        int r = t * H_SZ + hi0 + j;
        float w = (k < KIN) ? W_ih[(size_t)r * KIN + k]
                            : W_hh[(size_t)r * H_SZ + (k - KIN)];
        wsm[((size_t)j * K + k) * 4 + t] = w;
    }
    if (tid < 32) {
        int t = tid >> 3, j = tid & 7;
        int r = t * H_SZ + hi0 + j;
        bsm[j * 4 + t] = b_ih[r] + b_hh[r];
    }

    const int j = tid >> 5;
    const int lane = tid & 31;
    const int hi = hi0 + j;
    const int b0 = bbase + lane * 2;

    if (tid < 64) {                      // zero our h-slice rows (8 cols x 64 b)
        for (int jj = 0; jj < 8; ++jj)
            g_hbuf[0][(hi0 + jj) * B_SZ + bbase + tid] = 0.f;
    }

    // prefetch chunk 0 of step 0 (x-part: does not depend on h)
    {
        const float* src = inSeq + (size_t)0 * KIN * B_SZ + bbase;
#pragma unroll
        for (int u = 0; u < 4; ++u) {
            int op = u * 256 + tid;
            int row = op >> 4, seg = op & 15;
            cpa16(vbuf + row * 64 + seg * 4, src + (size_t)row * B_SZ + seg * 4);
        }
        CP_COMMIT();
    }
    __syncthreads();
    grid_barrier();

    float c0 = 0.f, c1 = 0.f;
    const float* wj = wsm + (size_t)j * K * 4;
    int nb = 1;                                    // next buffer to fill

    for (int st = 0; st < S_LEN; ++st) {
        const float* hprev = g_hbuf[st & 1];
        float* hOut = g_hbuf[(st + 1) & 1];

        float4 b4 = *(const float4*)&bsm[j * 4];
        ull a0 = dup2(b4.x), a1 = dup2(b4.y), a2 = dup2(b4.z), a3 = dup2(b4.w);

        for (int ci = 0; ci < NCH; ++ci) {
            // issue next chunk
            bool issued = true;
            const float* src;
            if (ci + 1 < NCH) {
                int k0 = (ci + 1) * CHUNK;
                src = (k0 < KIN) ? inSeq + ((size_t)st * KIN + k0) * B_SZ + bbase
                                 : hprev + (size_t)(k0 - KIN) * B_SZ + bbase;
            } else if (st + 1 < S_LEN) {
                src = inSeq + (size_t)(st + 1) * KIN * B_SZ + bbase;  // x-part
            } else {
                issued = false; src = 0;
            }
            if (issued) {
                float* dst = vbuf + nb * (CHUNK * 64);
#pragma unroll
                for (int u = 0; u < 4; ++u) {
                    int op = u * 256 + tid;
                    int row = op >> 4, seg = op & 15;
                    cpa16(dst + row * 64 + seg * 4, src + (size_t)row * B_SZ + seg * 4);
                }
                CP_COMMIT();
                nb ^= 1;
            }
            if (issued) CP_WAIT1(); else CP_WAIT0();
            __syncthreads();

            // compute on the READY buffer:
            //  - if we just issued and toggled, ready = nb (old buffer)
            //  - if nothing issued (final chunk), ready = nb^1 (last filled)
            const float* cur = vbuf + (issued ? nb : (nb ^ 1)) * (CHUNK * 64);
            const float* wk = wj + (size_t)ci * CHUNK * 4;
#pragma unroll 8
            for (int kk = 0; kk < CHUNK; ++kk) {
                float2 v = *(const float2*)(cur + kk * 64 + lane * 2);
                ull v2 = pk2(v.x, v.y);
                float4 w4 = *(const float4*)(wk + kk * 4);
                a0 = fma2(dup2(w4.x), v2, a0);
                a1 = fma2(dup2(w4.y), v2, a1);
                a2 = fma2(dup2(w4.z), v2, a2);
                a3 = fma2(dup2(w4.w), v2, a3);
            }
            __syncthreads();
        }

        float gi0, gi1, gf0, gf1, gg0, gg1, go0, go1;
        unpk(a0, gi0, gi1); unpk(a1, gf0, gf1);
        unpk(a2, gg0, gg1); unpk(a3, go0, go1);
        float cn0 = sigf(gf0) * c0 + sigf(gi0) * tanhf(gg0);
        float cn1 = sigf(gf1) * c1 + sigf(gi1) * tanhf(gg1);
        float h0 = sigf(go0) * tanhf(cn0);
        float h1 = sigf(go1) * tanhf(cn1);
        c0 = cn0; c1 = cn1;
        float2 h2v = make_float2(h0, h1);
        *(float2*)&hOut[hi * B_SZ + b0] = h2v;
        *(float2*)&outSeq[(size_t)st * H_SZ * B_SZ + (size_t)hi * B_SZ + b0] = h2v;

        grid_barrier();
    }
}

// ------------------------- attention energies --------------------------------
__global__ __launch_bounds__(256) void energy_kernel(
    const float* __restrict__ Wa, const float* __restrict__ ba,
    const float* __restrict__ va, const float* __restrict__ bv)
{
    const int s = blockIdx.x;
    const int tid = threadIdx.x;
    const int tx = tid & 15, ty = tid >> 4;
    __shared__ float sWa[32][132];
    __shared__ float sIn[32][132];
    __shared__ float red[16][128];
    const float* h2s = g_h2 + (size_t)s * H_SZ * B_SZ;

    float epart[8];
#pragma unroll
    for (int q = 0; q < 8; ++q) epart[q] = 0.f;

    for (int gc = 0; gc < 4; ++gc) {
        const int g0 = gc * 128;
        float acc[8][8];
#pragma unroll
        for (int i = 0; i < 8; ++i)
#pragma unroll
            for (int q = 0; q < 8; ++q) acc[i][q] = 0.f;

        for (int kt = 0; kt < 16; ++kt) {
            const int k0 = kt * 32;
            __syncthreads();
            for (int idx = tid; idx < 4096; idx += 256) {
                int gg = idx >> 5, kk = idx & 31;
                sWa[kk][gg] = Wa[(size_t)(g0 + gg) * H_SZ + k0 + kk];
            }
            for (int idx = tid; idx < 4096; idx += 256) {
                int kk = idx >> 7, bb = idx & 127;
                sIn[kk][bb] = h2s[(size_t)(k0 + kk) * B_SZ + bb];
            }
            __syncthreads();
#pragma unroll 4
            for (int k = 0; k < 32; ++k) {
                float4 w0 = *(float4*)&sWa[k][tx * 8];
                float4 w1 = *(float4*)&sWa[k][tx * 8 + 4];
                float4 i0 = *(float4*)&sIn[k][ty * 8];
                float4 i1 = *(float4*)&sIn[k][ty * 8 + 4];
                float wv[8] = {w0.x, w0.y, w0.z, w0.w, w1.x, w1.y, w1.z, w1.w};
                float iv[8] = {i0.x, i0.y, i0.z, i0.w, i1.x, i1.y, i1.z, i1.w};
#pragma unroll
                for (int i = 0; i < 8; ++i)
#pragma unroll
                    for (int q = 0; q < 8; ++q) acc[i][q] += wv[i] * iv[q];
            }
        }
#pragma unroll
        for (int i = 0; i < 8; ++i) {
            int gidx = g0 + tx * 8 + i;
            float gv = va[gidx], bav = ba[gidx];
#pragma unroll
            for (int q = 0; q < 8; ++q) epart[q] += gv * tanhf(acc[i][q] + bav);
        }
    }
    __syncthreads();
#pragma unroll
    for (int q = 0; q < 8; ++q) red[tx][ty * 8 + q] = epart[q];
    __syncthreads();
    if (tid < 128) {
        float e = bv[0];
#pragma unroll
        for (int t = 0; t < 16; ++t) e += red[t][tid];
        g_e[(size_t)tid * S_LEN + s] = e;
    }
}

// ------------------------- entmax15 (faithful to reference) ------------------
__global__ __launch_bounds__(512) void entmax_kernel(float* __restrict__ dout)
{
    const int b = blockIdx.x;
    const int tid = threadIdx.x;
    __shared__ float xs[1024], xo[1024], sa[1024], sb[1024];
    __shared__ float rf[512];
    __shared__ int ri[512];
    const float* row = g_e + (size_t)b * S_LEN;

    xo[tid] = row[tid];
    xo[tid + 512] = row[tid + 512];
    __syncthreads();
    rf[tid] = fmaxf(xo[tid], xo[tid + 512]);
    __syncthreads();
    for (int off = 256; off > 0; off >>= 1) {
        if (tid < off) rf[tid] = fmaxf(rf[tid], rf[tid + off]);
        __syncthreads();
    }
    float mx = rf[0];
    __syncthreads();
    xo[tid] -= mx; xo[tid + 512] -= mx;
    xs[tid] = xo[tid]; xs[tid + 512] = xo[tid + 512];
    __syncthreads();

    for (int k = 2; k <= 1024; k <<= 1) {
        for (int jj = k >> 1; jj > 0; jj >>= 1) {
            for (int i = tid; i < 1024; i += 512) {
                int ixj = i ^ jj;
                if (ixj > i) {
                    bool up = ((i & k) == 0);
                    float a = xs[i], c2 = xs[ixj];
                    bool sw = up ? (a < c2) : (a > c2);
                    if (sw) { xs[i] = c2; xs[ixj] = a; }
                }
            }
            __syncthreads();
        }
    }

    sa[tid] = xs[tid]; sa[tid + 512] = xs[tid + 512];
    __syncthreads();
    float* pa = sa; float* pb = sb;
    for (int off = 1; off < 1024; off <<= 1) {
        for (int i = tid; i < 1024; i += 512)
            pb[i] = pa[i] + ((i >= off) ? pa[i - off] : 0.f);
        __syncthreads();
        float* t = pa; pa = pb; pb = t;
    }

    int cnt = 0;
    for (int i = tid; i < 1024; i += 512) {
        float sup = (float)(i + 1) * xs[i] - pa[i] + 0.5f;
        if (sup > 0.f) cnt++;
    }
    ri[tid] = cnt;
    __syncthreads();
    for (int off = 256; off > 0; off >>= 1) {
        if (tid < off) ri[tid] += ri[tid + off];
        __syncthreads();
    }
    int ssize = ri[0];
    if (ssize < 1) ssize = 1;
    if (ssize > 1023) ssize = 1023;
    float tau = ((float)(ssize + 1) * xs[ssize] - pa[ssize] + 0.5f) / (float)(ssize + 1);

    float d0 = xo[tid] - tau;
    float d1 = xo[tid + 512] - tau;
    float y0 = d0 > 0.f ? sqrtf(d0) : 0.f;
    float y1 = d1 > 0.f ? sqrtf(d1) : 0.f;
    __syncthreads();
    rf[tid] = y0 + y1;
    __syncthreads();
    for (int off = 256; off > 0; off >>= 1) {
        if (tid < off) rf[tid] += rf[tid + off];
        __syncthreads();
    }
    float inv = 1.f / rf[0];
    float w0 = y0 * inv, w1 = y1 * inv;
    g_att[(size_t)b * S_LEN + tid] = w0;
    g_att[(size_t)b * S_LEN + tid + 512] = w1;
    dout[128 + (size_t)b * S_LEN + tid] = w0;
    dout[128 + (size_t)b * S_LEN + tid + 512] = w1;
}

// ------------------------- context stage 1 -----------------------------------
__global__ __launch_bounds__(256) void ctx1_kernel()
{
    __shared__ float sAtt[64 * 128];
    const int bid = blockIdx.x;
    const int ch = bid >> 2, hq = bid & 3;
    const int s0 = ch * 64, h0 = hq * 128;
    const int tid = threadIdx.x;

    for (int idx = tid; idx < 64 * 128; idx += 256) {
        int sl = idx >> 7, bb = idx & 127;
        sAtt[idx] = g_att[(size_t)bb * S_LEN + s0 + sl];
    }
    __syncthreads();

    float racc[64];
#pragma unroll
    for (int u = 0; u < 64; ++u) racc[u] = 0.f;

    const int bcol = tid & 127;
    for (int sl = 0; sl < 64; ++sl) {
        const float* src = g_h2 + ((size_t)(s0 + sl) * H_SZ + h0) * B_SZ;
        float av = sAtt[sl * 128 + bcol];
#pragma unroll 8
        for (int u = 0; u < 64; ++u)
            racc[u] += av * __ldg(src + tid + u * 256);
    }
#pragma unroll
    for (int u = 0; u < 64; ++u)
        g_pc[(size_t)bid * 16384 + tid + u * 256] = racc[u];
}

// ------------------------- context stage 2 + FC ------------------------------
__global__ void ctx2_kernel()
{
    int e = blockIdx.x * 256 + threadIdx.x;
    if (e < H_SZ * B_SZ) {
        int h = e >> 7, bb = e & 127;
        int hq = h >> 7, hl = h & 127;
        float s = 0.f;
#pragma unroll
        for (int ch = 0; ch < 16; ++ch)
            s += g_pc[((size_t)(ch * 4 + hq) * 16384) + hl * 128 + bb];
        g_ctx[e] = s;
    }
}

__global__ void fc_kernel(const float* __restrict__ fcW,
                          const float* __restrict__ fcb,
                          float* __restrict__ out)
{
    int b = threadIdx.x;
    float a = fcb[0];
    for (int h = 0; h < H_SZ; ++h) a += fcW[h] * g_ctx[h * B_SZ + b];
    out[b] = a;
}

// ------------------------- launch --------------------------------------------
extern "C" void kernel_launch(void* const* d_in, const int* in_sizes, int n_in,
                              void* d_out, int out_size)
{
    (void)in_sizes; (void)n_in; (void)out_size;
    const float* x     = (const float*)d_in[0];
    const float* W_ih0 = (const float*)d_in[1];
    const float* W_hh0 = (const float*)d_in[2];
    const float* b_ih0 = (const float*)d_in[3];
    const float* b_hh0 = (const float*)d_in[4];
    const float* W_ih1 = (const float*)d_in[5];
    const float* W_hh1 = (const float*)d_in[6];
    const float* b_ih1 = (const float*)d_in[7];
    const float* b_hh1 = (const float*)d_in[8];
    const float* W_a   = (const float*)d_in[9];
    const float* b_a   = (const float*)d_in[10];
    const float* v_a   = (const float*)d_in[11];
    const float* b_v   = (const float*)d_in[12];
    const float* fc_W  = (const float*)d_in[13];
    const float* fc_b  = (const float*)d_in[14];
    float* out = (float*)d_out;

    const int smem0 = (32 * (D_IN + H_SZ) + 2 * CHUNK * 64) * 4;   // 106,496 B
    const int smem1 = (32 * (H_SZ + H_SZ) + 2 * CHUNK * 64) * 4;   // 163,840 B
    cudaFuncSetAttribute(lstm_kernel<D_IN>, cudaFuncAttributeMaxDynamicSharedMemorySize, smem0);
    cudaFuncSetAttribute(lstm_kernel<H_SZ>, cudaFuncAttributeMaxDynamicSharedMemorySize, smem1);

    transpose_kernel<<<(S_LEN * D_IN * B_SZ + 255) / 256, 256>>>(x);
    lstm_kernel<D_IN><<<NCTA, 256, smem0>>>(W_ih0, W_hh0, b_ih0, b_hh0);
    lstm_kernel<H_SZ><<<NCTA, 256, smem1>>>(W_ih1, W_hh1, b_ih1, b_hh1);
    energy_kernel<<<S_LEN, 256>>>(W_a, b_a, v_a, b_v);
    entmax_kernel<<<B_SZ, 512>>>(out);
    ctx1_kernel<<<64, 256>>>();
    ctx2_kernel<<<(H_SZ * B_SZ + 255) / 256, 256>>>();
    fc_kernel<<<1, 128>>>(fc_W, fc_b, out);
}

// round 8
// speedup vs baseline: 3.3475x; 1.0011x over previous
#include <cuda_runtime.h>
#include <math.h>

#define S_LEN 1024
#define B_SZ  128
#define D_IN  64
#define H_SZ  512
#define NCTA  128
#define CHUNK 64

typedef unsigned long long ull;

// ------------------------- device scratch (allocation-free rule) -------------
__device__ float g_xT[S_LEN * D_IN * B_SZ];                 // [S][D][B]   32 MB
__device__ float g_h1[(size_t)S_LEN * H_SZ * B_SZ];         // [S][H][B]  256 MB
__device__ float g_h2[(size_t)S_LEN * H_SZ * B_SZ];         // [S][H][B]  256 MB
__device__ float g_hbuf[2][H_SZ * B_SZ];                    // double-buffered h
__device__ float g_e[B_SZ * S_LEN];                         // energies [B][S]
__device__ float g_att[B_SZ * S_LEN];                       // entmax weights
__device__ float g_pc[64 * 128 * 128];                      // partial contexts
__device__ float g_ctx[H_SZ * B_SZ];                        // context [H][B]
__device__ unsigned g_bar_count;
__device__ unsigned g_bar_gen;

// ------------------------- f32x2 helpers -------------------------------------
__device__ __forceinline__ ull dup2(float v) {
    ull r; asm("mov.b64 %0, {%1, %1};" : "=l"(r) : "f"(v)); return r;
}
__device__ __forceinline__ ull pk2(float lo, float hi) {
    ull r; asm("mov.b64 %0, {%1, %2};" : "=l"(r) : "f"(lo), "f"(hi)); return r;
}
__device__ __forceinline__ void unpk(ull v, float& lo, float& hi) {
    asm("mov.b64 {%0, %1}, %2;" : "=f"(lo), "=f"(hi) : "l"(v));
}
__device__ __forceinline__ ull fma2(ull a, ull b, ull c) {
    ull d; asm("fma.rn.f32x2 %0, %1, %2, %3;" : "=l"(d) : "l"(a), "l"(b), "l"(c));
    return d;
}
__device__ __forceinline__ float sigf(float v) { return 1.0f / (1.0f + expf(-v)); }

// ------------------------- cp.async helpers ----------------------------------
__device__ __forceinline__ void cpa16(float* smem_dst, const float* gmem_src) {
    unsigned s = (unsigned)__cvta_generic_to_shared(smem_dst);
    asm volatile("cp.async.cg.shared.global [%0], [%1], 16;" :: "r"(s), "l"(gmem_src));
}
#define CP_COMMIT() asm volatile("cp.async.commit_group;" ::: "memory")
#define CP_WAIT1()  asm volatile("cp.async.wait_group 1;" ::: "memory")
#define CP_WAIT0()  asm volatile("cp.async.wait_group 0;" ::: "memory")

// ------------------------- grid barrier (proven in R5) -----------------------
__device__ __forceinline__ unsigned gen_read() {
    unsigned v;
    asm volatile("ld.acquire.gpu.u32 %0, [%1];" : "=r"(v) : "l"(&g_bar_gen) : "memory");
    return v;
}
__device__ __forceinline__ void grid_barrier() {
    __syncthreads();
    if (threadIdx.x == 0) {
        unsigned target = gen_read() + 1u;          // read BEFORE arriving
        __threadfence();
        unsigned old = atomicAdd(&g_bar_count, 1u);
        if (old == NCTA - 1u) {
            atomicExch(&g_bar_count, 0u);
            __threadfence();
            atomicExch(&g_bar_gen, target);         // publish release
        } else {
            while ((int)(gen_read() - target) < 0) { __nanosleep(32); }
        }
        __threadfence();
    }
    __syncthreads();
}

// ------------------------- transpose x[B][S][D] -> xT[S][D][B] ---------------
__global__ void transpose_kernel(const float* __restrict__ x) {
    int idx = blockIdx.x * 256 + threadIdx.x;
    if (idx < S_LEN * D_IN * B_SZ) {
        int b = idx & (B_SZ - 1);
        int sd = idx >> 7;
        int d = sd & (D_IN - 1);
        int s = sd >> 6;
        g_xT[idx] = x[((size_t)b * S_LEN + s) * D_IN + d];
    }
}

// ------------------------- persistent LSTM layer -----------------------------
// CTA = 8 h-columns x 64 batches -> 32 gate rows. Weights in SMEM, layout
// [j][k][4 gates]: each k's 4 gate weights are one 16B-aligned LDS.128, and
// (i,f) / (g,o) are the natural 64-bit halves for fma.f32x2.
// 256 threads: j = tid>>5 (h-col 0..7), lane = tid&31, 2 batches per thread.
template <int KIN>
__global__ __launch_bounds__(256, 1) void lstm_kernel(
    const float* __restrict__ W_ih, const float* __restrict__ W_hh,
    const float* __restrict__ b_ih, const float* __restrict__ b_hh)
{
    constexpr int K = KIN + H_SZ;
    constexpr int NCH = K / CHUNK;
    extern __shared__ float wsm[];                 // [8 j][K][4 t]
    float* vbuf = wsm + 32 * K;                    // 2 x [CHUNK][64]
    __shared__ float bsm[32];                      // [j][4 t]

    const float* inSeq = (KIN == D_IN) ? g_xT : g_h1;
    float* outSeq      = (KIN == D_IN) ? g_h1 : g_h2;

    const int tid = threadIdx.x;
    const int cid = blockIdx.x;
    const int hg = cid >> 1;
    const int bg = cid & 1;
    const int hi0 = hg * 8;
    const int bbase = bg * 64;

    // weights: gate row r = t*H + hi0 + j, element k -> wsm[(j*K + k)*4 + t]
    for (int idx = tid; idx < 32 * K; idx += 256) {
        int row = idx / K;              // row = t*8 + j
        int k = idx - row * K;
        int t = row >> 3, j = row & 7;
        int r = t * H_SZ + hi0 + j;
        float w = (k < KIN) ? W_ih[(size_t)r * KIN + k]
                            : W_hh[(size_t)r * H_SZ + (k - KIN)];
        wsm[((size_t)j * K + k) * 4 + t] = w;
    }
    if (tid < 32) {
        int t = tid >> 3, j = tid & 7;
        int r = t * H_SZ + hi0 + j;
        bsm[j * 4 + t] = b_ih[r] + b_hh[r];
    }

    const int j = tid >> 5;
    const int lane = tid & 31;
    const int hi = hi0 + j;
    const int b0 = bbase + lane * 2;

    if (tid < 64) {                      // zero our h-slice rows (8 cols x 64 b)
        for (int jj = 0; jj < 8; ++jj)
            g_hbuf[0][(hi0 + jj) * B_SZ + bbase + tid] = 0.f;
    }

    // prefetch chunk 0 of step 0 (x-part: does not depend on h)
    {
        const float* src = inSeq + (size_t)0 * KIN * B_SZ + bbase;
#pragma unroll
        for (int u = 0; u < 4; ++u) {
            int op = u * 256 + tid;
            int row = op >> 4, seg = op & 15;
            cpa16(vbuf + row * 64 + seg * 4, src + (size_t)row * B_SZ + seg * 4);
        }
        CP_COMMIT();
    }
    __syncthreads();
    grid_barrier();

    // hoist biases into registers (scalar shared loads; no vector-load of bsm)
    float bi_i = bsm[j * 4 + 0];
    float bi_f = bsm[j * 4 + 1];
    float bi_g = bsm[j * 4 + 2];
    float bi_o = bsm[j * 4 + 3];
    const ull binit_if = pk2(bi_i, bi_f);
    const ull binit_go = pk2(bi_g, bi_o);

    float c0 = 0.f, c1 = 0.f;
    const float* wj = wsm + (size_t)j * K * 4;
    int nb = 1;                                    // next buffer to fill

    for (int st = 0; st < S_LEN; ++st) {
        const float* hprev = g_hbuf[st & 1];
        float* hOut = g_hbuf[(st + 1) & 1];

        ull aif0 = binit_if, ago0 = binit_go;
        ull aif1 = binit_if, ago1 = binit_go;

        for (int ci = 0; ci < NCH; ++ci) {
            // issue next chunk
            bool issued = true;
            const float* src;
            if (ci + 1 < NCH) {
                int k0 = (ci + 1) * CHUNK;
                src = (k0 < KIN) ? inSeq + ((size_t)st * KIN + k0) * B_SZ + bbase
                                 : hprev + (size_t)(k0 - KIN) * B_SZ + bbase;
            } else if (st + 1 < S_LEN) {
                src = inSeq + (size_t)(st + 1) * KIN * B_SZ + bbase;  // x-part
            } else {
                issued = false; src = 0;
            }
            if (issued) {
                float* dst = vbuf + nb * (CHUNK * 64);
#pragma unroll
                for (int u = 0; u < 4; ++u) {
                    int op = u * 256 + tid;
                    int row = op >> 4, seg = op & 15;
                    cpa16(dst + row * 64 + seg * 4, src + (size_t)row * B_SZ + seg * 4);
                }
                CP_COMMIT();
                nb ^= 1;
            }
            if (issued) CP_WAIT1(); else CP_WAIT0();
            __syncthreads();

            // compute on the READY buffer (nb if just toggled, nb^1 otherwise)
            const float* cur = vbuf + (issued ? nb : (nb ^ 1)) * (CHUNK * 64);
            const ulonglong2* wk =
                (const ulonglong2*)(wj + (size_t)ci * CHUNK * 4);
#pragma unroll 8
            for (int kk = 0; kk < CHUNK; ++kk) {
                float2 v = *(const float2*)(cur + kk * 64 + lane * 2);
                ull v0 = dup2(v.x), v1 = dup2(v.y);
                ulonglong2 w2 = wk[kk];            // LDS.128: (wi,wf),(wg,wo)
                aif0 = fma2(w2.x, v0, aif0);
                ago0 = fma2(w2.y, v0, ago0);
                aif1 = fma2(w2.x, v1, aif1);
                ago1 = fma2(w2.y, v1, ago1);
            }
            __syncthreads();
        }

        float gi0, gf0, gg0, go0, gi1, gf1, gg1, go1;
        unpk(aif0, gi0, gf0); unpk(ago0, gg0, go0);
        unpk(aif1, gi1, gf1); unpk(ago1, gg1, go1);
        float cn0 = sigf(gf0) * c0 + sigf(gi0) * tanhf(gg0);
        float cn1 = sigf(gf1) * c1 + sigf(gi1) * tanhf(gg1);
        float h0 = sigf(go0) * tanhf(cn0);
        float h1 = sigf(go1) * tanhf(cn1);
        c0 = cn0; c1 = cn1;
        float2 h2v = make_float2(h0, h1);
        *(float2*)&hOut[hi * B_SZ + b0] = h2v;
        *(float2*)&outSeq[(size_t)st * H_SZ * B_SZ + (size_t)hi * B_SZ + b0] = h2v;

        grid_barrier();
    }
}

// ------------------------- attention energies --------------------------------
__global__ __launch_bounds__(256) void energy_kernel(
    const float* __restrict__ Wa, const float* __restrict__ ba,
    const float* __restrict__ va, const float* __restrict__ bv)
{
    const int s = blockIdx.x;
    const int tid = threadIdx.x;
    const int tx = tid & 15, ty = tid >> 4;
    __shared__ float sWa[32][132];
    __shared__ float sIn[32][132];
    __shared__ float red[16][128];
    const float* h2s = g_h2 + (size_t)s * H_SZ * B_SZ;

    float epart[8];
#pragma unroll
    for (int q = 0; q < 8; ++q) epart[q] = 0.f;

    for (int gc = 0; gc < 4; ++gc) {
        const int g0 = gc * 128;
        float acc[8][8];
#pragma unroll
        for (int i = 0; i < 8; ++i)
#pragma unroll
            for (int q = 0; q < 8; ++q) acc[i][q] = 0.f;

        for (int kt = 0; kt < 16; ++kt) {
            const int k0 = kt * 32;
            __syncthreads();
            for (int idx = tid; idx < 4096; idx += 256) {
                int gg = idx >> 5, kk = idx & 31;
                sWa[kk][gg] = Wa[(size_t)(g0 + gg) * H_SZ + k0 + kk];
            }
            for (int idx = tid; idx < 4096; idx += 256) {
                int kk = idx >> 7, bb = idx & 127;
                sIn[kk][bb] = h2s[(size_t)(k0 + kk) * B_SZ + bb];
            }
            __syncthreads();
#pragma unroll 4
            for (int k = 0; k < 32; ++k) {
                float4 w0 = *(float4*)&sWa[k][tx * 8];
                float4 w1 = *(float4*)&sWa[k][tx * 8 + 4];
                float4 i0 = *(float4*)&sIn[k][ty * 8];
                float4 i1 = *(float4*)&sIn[k][ty * 8 + 4];
                float wv[8] = {w0.x, w0.y, w0.z, w0.w, w1.x, w1.y, w1.z, w1.w};
                float iv[8] = {i0.x, i0.y, i0.z, i0.w, i1.x, i1.y, i1.z, i1.w};
#pragma unroll
                for (int i = 0; i < 8; ++i)
#pragma unroll
                    for (int q = 0; q < 8; ++q) acc[i][q] += wv[i] * iv[q];
            }
        }
#pragma unroll
        for (int i = 0; i < 8; ++i) {
            int gidx = g0 + tx * 8 + i;
            float gv = va[gidx], bav = ba[gidx];
#pragma unroll
            for (int q = 0; q < 8; ++q) epart[q] += gv * tanhf(acc[i][q] + bav);
        }
    }
    __syncthreads();
#pragma unroll
    for (int q = 0; q < 8; ++q) red[tx][ty * 8 + q] = epart[q];
    __syncthreads();
    if (tid < 128) {
        float e = bv[0];
#pragma unroll
        for (int t = 0; t < 16; ++t) e += red[t][tid];
        g_e[(size_t)tid * S_LEN + s] = e;
    }
}

// ------------------------- entmax15 (faithful to reference) ------------------
__global__ __launch_bounds__(512) void entmax_kernel(float* __restrict__ dout)
{
    const int b = blockIdx.x;
    const int tid = threadIdx.x;
    __shared__ float xs[1024], xo[1024], sa[1024], sb[1024];
    __shared__ float rf[512];
    __shared__ int ri[512];
    const float* row = g_e + (size_t)b * S_LEN;

    xo[tid] = row[tid];
    xo[tid + 512] = row[tid + 512];
    __syncthreads();
    rf[tid] = fmaxf(xo[tid], xo[tid + 512]);
    __syncthreads();
    for (int off = 256; off > 0; off >>= 1) {
        if (tid < off) rf[tid] = fmaxf(rf[tid], rf[tid + off]);
        __syncthreads();
    }
    float mx = rf[0];
    __syncthreads();
    xo[tid] -= mx; xo[tid + 512] -= mx;
    xs[tid] = xo[tid]; xs[tid + 512] = xo[tid + 512];
    __syncthreads();

    for (int k = 2; k <= 1024; k <<= 1) {
        for (int jj = k >> 1; jj > 0; jj >>= 1) {
            for (int i = tid; i < 1024; i += 512) {
                int ixj = i ^ jj;
                if (ixj > i) {
                    bool up = ((i & k) == 0);
                    float a = xs[i], c2 = xs[ixj];
                    bool sw = up ? (a < c2) : (a > c2);
                    if (sw) { xs[i] = c2; xs[ixj] = a; }
                }
            }
            __syncthreads();
        }
    }

    sa[tid] = xs[tid]; sa[tid + 512] = xs[tid + 512];
    __syncthreads();
    float* pa = sa; float* pb = sb;
    for (int off = 1; off < 1024; off <<= 1) {
        for (int i = tid; i < 1024; i += 512)
            pb[i] = pa[i] + ((i >= off) ? pa[i - off] : 0.f);
        __syncthreads();
        float* t = pa; pa = pb; pb = t;
    }

    int cnt = 0;
    for (int i = tid; i < 1024; i += 512) {
        float sup = (float)(i + 1) * xs[i] - pa[i] + 0.5f;
        if (sup > 0.f) cnt++;
    }
    ri[tid] = cnt;
    __syncthreads();
    for (int off = 256; off > 0; off >>= 1) {
        if (tid < off) ri[tid] += ri[tid + off];
        __syncthreads();
    }
    int ssize = ri[0];
    if (ssize < 1) ssize = 1;
    if (ssize > 1023) ssize = 1023;
    float tau = ((float)(ssize + 1) * xs[ssize] - pa[ssize] + 0.5f) / (float)(ssize + 1);

    float d0 = xo[tid] - tau;
    float d1 = xo[tid + 512] - tau;
    float y0 = d0 > 0.f ? sqrtf(d0) : 0.f;
    float y1 = d1 > 0.f ? sqrtf(d1) : 0.f;
    __syncthreads();
    rf[tid] = y0 + y1;
    __syncthreads();
    for (int off = 256; off > 0; off >>= 1) {
        if (tid < off) rf[tid] += rf[tid + off];
        __syncthreads();
    }
    float inv = 1.f / rf[0];
    float w0 = y0 * inv, w1 = y1 * inv;
    g_att[(size_t)b * S_LEN + tid] = w0;
    g_att[(size_t)b * S_LEN + tid + 512] = w1;
    dout[128 + (size_t)b * S_LEN + tid] = w0;
    dout[128 + (size_t)b * S_LEN + tid + 512] = w1;
}

// ------------------------- context stage 1 -----------------------------------
__global__ __launch_bounds__(256) void ctx1_kernel()
{
    __shared__ float sAtt[64 * 128];
    const int bid = blockIdx.x;
    const int ch = bid >> 2, hq = bid & 3;
    const int s0 = ch * 64, h0 = hq * 128;
    const int tid = threadIdx.x;

    for (int idx = tid; idx < 64 * 128; idx += 256) {
        int sl = idx >> 7, bb = idx & 127;
        sAtt[idx] = g_att[(size_t)bb * S_LEN + s0 + sl];
    }
    __syncthreads();

    float racc[64];
#pragma unroll
    for (int u = 0; u < 64; ++u) racc[u] = 0.f;

    const int bcol = tid & 127;
    for (int sl = 0; sl < 64; ++sl) {
        const float* src = g_h2 + ((size_t)(s0 + sl) * H_SZ + h0) * B_SZ;
        float av = sAtt[sl * 128 + bcol];
#pragma unroll 8
        for (int u = 0; u < 64; ++u)
            racc[u] += av * __ldg(src + tid + u * 256);
    }
#pragma unroll
    for (int u = 0; u < 64; ++u)
        g_pc[(size_t)bid * 16384 + tid + u * 256] = racc[u];
}

// ------------------------- context stage 2 + FC ------------------------------
__global__ void ctx2_kernel()
{
    int e = blockIdx.x * 256 + threadIdx.x;
    if (e < H_SZ * B_SZ) {
        int h = e >> 7, bb = e & 127;
        int hq = h >> 7, hl = h & 127;
        float s = 0.f;
#pragma unroll
        for (int ch = 0; ch < 16; ++ch)
            s += g_pc[((size_t)(ch * 4 + hq) * 16384) + hl * 128 + bb];
        g_ctx[e] = s;
    }
}

__global__ void fc_kernel(const float* __restrict__ fcW,
                          const float* __restrict__ fcb,
                          float* __restrict__ out)
{
    int b = threadIdx.x;
    float a = fcb[0];
    for (int h = 0; h < H_SZ; ++h) a += fcW[h] * g_ctx[h * B_SZ + b];
    out[b] = a;
}

// ------------------------- launch --------------------------------------------
extern "C" void kernel_launch(void* const* d_in, const int* in_sizes, int n_in,
                              void* d_out, int out_size)
{
    (void)in_sizes; (void)n_in; (void)out_size;
    const float* x     = (const float*)d_in[0];
    const float* W_ih0 = (const float*)d_in[1];
    const float* W_hh0 = (const float*)d_in[2];
    const float* b_ih0 = (const float*)d_in[3];
    const float* b_hh0 = (const float*)d_in[4];
    const float* W_ih1 = (const float*)d_in[5];
    const float* W_hh1 = (const float*)d_in[6];
    const float* b_ih1 = (const float*)d_in[7];
    const float* b_hh1 = (const float*)d_in[8];
    const float* W_a   = (const float*)d_in[9];
    const float* b_a   = (const float*)d_in[10];
    const float* v_a   = (const float*)d_in[11];
    const float* b_v   = (const float*)d_in[12];
    const float* fc_W  = (const float*)d_in[13];
    const float* fc_b  = (const float*)d_in[14];
    float* out = (float*)d_out;

    const int smem0 = (32 * (D_IN + H_SZ) + 2 * CHUNK * 64) * 4;   // 106,496 B
    const int smem1 = (32 * (H_SZ + H_SZ) + 2 * CHUNK * 64) * 4;   // 163,840 B
    cudaFuncSetAttribute(lstm_kernel<D_IN>, cudaFuncAttributeMaxDynamicSharedMemorySize, smem0);
    cudaFuncSetAttribute(lstm_kernel<H_SZ>, cudaFuncAttributeMaxDynamicSharedMemorySize, smem1);

    transpose_kernel<<<(S_LEN * D_IN * B_SZ + 255) / 256, 256>>>(x);
    lstm_kernel<D_IN><<<NCTA, 256, smem0>>>(W_ih0, W_hh0, b_ih0, b_hh0);
    lstm_kernel<H_SZ><<<NCTA, 256, smem1>>>(W_ih1, W_hh1, b_ih1, b_hh1);
    energy_kernel<<<S_LEN, 256>>>(W_a, b_a, v_a, b_v);
    entmax_kernel<<<B_SZ, 512>>>(out);
    ctx1_kernel<<<64, 256>>>();
    ctx2_kernel<<<(H_SZ * B_SZ + 255) / 256, 256>>>();
    fc_kernel<<<1, 128>>>(fc_W, fc_b, out);
}